// round 1
// baseline (speedup 1.0000x reference)
#include <cuda_runtime.h>
#include <math.h>

#define T_TOK  8192
#define DMODEL 1024
#define HDIM   2048
#define NEXP   8
#define CAP    8192   // per-expert slot capacity (top-2 => each list <= T)

// ---------------- device scratch (static, allocation-free) ----------------
__device__ int   g_cnt[NEXP];
__device__ int   g_tok[NEXP * CAP];
__device__ float g_gate[NEXP * CAP];
__device__ float g_h[(size_t)NEXP * CAP * HDIM];   // 512 MiB SwiGLU activations

// ---------------------------------------------------------------------------
// Router: one warp per token. Computes router & noise logits, noisy top-2,
// softmax-over-2 gates, appends token into per-expert compacted lists.
// ---------------------------------------------------------------------------
__global__ void __launch_bounds__(128) k_router(
    const float* __restrict__ x, const float* __restrict__ noise,
    const float* __restrict__ rw, const float* __restrict__ rb,
    const float* __restrict__ nw, const float* __restrict__ nb)
{
    const int warp = threadIdx.x >> 5;
    const int lane = threadIdx.x & 31;
    const int t = blockIdx.x * 4 + warp;           // grid = 2048 blocks * 4 warps = 8192

    const float* xr = x + (size_t)t * DMODEL;

    float accR[NEXP], accN[NEXP];
#pragma unroll
    for (int j = 0; j < NEXP; j++) { accR[j] = 0.f; accN[j] = 0.f; }

    for (int d = lane; d < DMODEL; d += 32) {
        const float xv = xr[d];
#pragma unroll
        for (int j = 0; j < NEXP; j++) {
            accR[j] += xv * rw[j * DMODEL + d];
            accN[j] += xv * nw[j * DMODEL + d];
        }
    }
#pragma unroll
    for (int j = 0; j < NEXP; j++) {
#pragma unroll
        for (int o = 16; o > 0; o >>= 1) {
            accR[j] += __shfl_xor_sync(0xffffffffu, accR[j], o);
            accN[j] += __shfl_xor_sync(0xffffffffu, accN[j], o);
        }
    }

    if (lane == 0) {
        float noisy[NEXP];
#pragma unroll
        for (int j = 0; j < NEXP; j++) {
            const float z  = accN[j] + nb[j];
            const float sp = (z > 20.f) ? z : log1pf(expf(z));   // softplus
            noisy[j] = accR[j] + rb[j] + noise[(size_t)t * NEXP + j] * sp;
        }
        // top-2 (ties -> lower index, matching jax.lax.top_k)
        int i0 = 0;
#pragma unroll
        for (int j = 1; j < NEXP; j++) if (noisy[j] > noisy[i0]) i0 = j;
        int i1 = (i0 == 0) ? 1 : 0;
#pragma unroll
        for (int j = 0; j < NEXP; j++)
            if (j != i0 && noisy[j] > noisy[i1]) i1 = j;

        const float v0 = noisy[i0], v1 = noisy[i1];
        const float g0 = 1.f / (1.f + expf(v1 - v0));
        const float g1 = 1.f / (1.f + expf(v0 - v1));

        int p0 = atomicAdd(&g_cnt[i0], 1);
        g_tok[i0 * CAP + p0]  = t;
        g_gate[i0 * CAP + p0] = g0;
        int p1 = atomicAdd(&g_cnt[i1], 1);
        g_tok[i1 * CAP + p1]  = t;
        g_gate[i1 * CAP + p1] = g1;
    }
}

// ---------------------------------------------------------------------------
// GEMM1 (fused w1 & w3 + SwiGLU): per expert, gathered rows.
// Tile 128(M) x 64(N) x 32(K), 256 threads, thread tile 8x4, two accumulators.
// h[slot, n] = silu(x . w1[e,n,:]) * (x . w3[e,n,:])
// ---------------------------------------------------------------------------
__global__ void __launch_bounds__(256, 2) k_gemm1(
    const float* __restrict__ x,
    const float* __restrict__ w1, const float* __restrict__ w3)
{
    const int e    = blockIdx.z;
    const int cnt  = g_cnt[e];
    const int row0 = blockIdx.x * 128;
    if (row0 >= cnt) return;
    const int n0 = blockIdx.y * 64;

    __shared__ float sA [32][128];
    __shared__ float sB1[32][64];
    __shared__ float sB3[32][64];

    const int tid    = threadIdx.x;
    const int m_base = (tid >> 4) << 3;   // 0..120
    const int n_base = (tid & 15) << 2;   // 0..60

    const int* tokp = g_tok + e * CAP + row0;
    const float* xrow[4];
#pragma unroll
    for (int i = 0; i < 4; i++) {
        const int q = tid + i * 256;
        const int r = q >> 3;
        const int tk = (row0 + r < cnt) ? tokp[r] : 0;   // guard stale/garbage slots
        xrow[i] = x + (size_t)tk * DMODEL + ((q & 7) << 2);
    }
    const float* w1p = w1 + ((size_t)e * HDIM + n0) * DMODEL;
    const float* w3p = w3 + ((size_t)e * HDIM + n0) * DMODEL;

    float acc1[8][4], acc3[8][4];
#pragma unroll
    for (int i = 0; i < 8; i++)
#pragma unroll
        for (int j = 0; j < 4; j++) { acc1[i][j] = 0.f; acc3[i][j] = 0.f; }

    for (int k0 = 0; k0 < DMODEL; k0 += 32) {
#pragma unroll
        for (int i = 0; i < 4; i++) {
            const int q = tid + i * 256;
            const int r = q >> 3, c = q & 7;
            const float4 v = *(const float4*)(xrow[i] + k0);
            sA[c * 4 + 0][r] = v.x; sA[c * 4 + 1][r] = v.y;
            sA[c * 4 + 2][r] = v.z; sA[c * 4 + 3][r] = v.w;
        }
#pragma unroll
        for (int i = 0; i < 2; i++) {
            const int q = tid + i * 256;
            const int n = q >> 3, c = q & 7;
            const float4 v = *(const float4*)(w1p + (size_t)n * DMODEL + k0 + (c << 2));
            sB1[c * 4 + 0][n] = v.x; sB1[c * 4 + 1][n] = v.y;
            sB1[c * 4 + 2][n] = v.z; sB1[c * 4 + 3][n] = v.w;
            const float4 u = *(const float4*)(w3p + (size_t)n * DMODEL + k0 + (c << 2));
            sB3[c * 4 + 0][n] = u.x; sB3[c * 4 + 1][n] = u.y;
            sB3[c * 4 + 2][n] = u.z; sB3[c * 4 + 3][n] = u.w;
        }
        __syncthreads();
#pragma unroll
        for (int kk = 0; kk < 32; kk++) {
            const float4 a0  = *(const float4*)&sA [kk][m_base];
            const float4 a1  = *(const float4*)&sA [kk][m_base + 4];
            const float4 b1v = *(const float4*)&sB1[kk][n_base];
            const float4 b3v = *(const float4*)&sB3[kk][n_base];
            const float a[8]  = {a0.x, a0.y, a0.z, a0.w, a1.x, a1.y, a1.z, a1.w};
            const float p1[4] = {b1v.x, b1v.y, b1v.z, b1v.w};
            const float p3[4] = {b3v.x, b3v.y, b3v.z, b3v.w};
#pragma unroll
            for (int mi = 0; mi < 8; mi++)
#pragma unroll
                for (int ni = 0; ni < 4; ni++) {
                    acc1[mi][ni] += a[mi] * p1[ni];
                    acc3[mi][ni] += a[mi] * p3[ni];
                }
        }
        __syncthreads();
    }

    float* hp = g_h + ((size_t)e * CAP + row0) * HDIM + n0;
#pragma unroll
    for (int mi = 0; mi < 8; mi++) {
        float4 o;
        float v;
        v = acc1[mi][0]; o.x = (v / (1.f + expf(-v))) * acc3[mi][0];
        v = acc1[mi][1]; o.y = (v / (1.f + expf(-v))) * acc3[mi][1];
        v = acc1[mi][2]; o.z = (v / (1.f + expf(-v))) * acc3[mi][2];
        v = acc1[mi][3]; o.w = (v / (1.f + expf(-v))) * acc3[mi][3];
        *(float4*)(hp + (size_t)(m_base + mi) * HDIM + n_base) = o;
    }
}

// ---------------------------------------------------------------------------
// GEMM2: out[t, d] += gate * (h[slot,:] . w2[e,d,:]).
// Tile 128(M) x 128(N) x 32(K), 256 threads, thread tile 8x8.
// Exactly two atomicAdds land on each zeroed output element -> deterministic.
// ---------------------------------------------------------------------------
__global__ void __launch_bounds__(256, 2) k_gemm2(
    const float* __restrict__ w2, float* __restrict__ out)
{
    const int e    = blockIdx.z;
    const int cnt  = g_cnt[e];
    const int row0 = blockIdx.x * 128;
    if (row0 >= cnt) return;
    const int n0 = blockIdx.y * 128;

    __shared__ float sA[32][128];
    __shared__ float sB[32][128];

    const int tid    = threadIdx.x;
    const int m_base = (tid >> 4) << 3;
    const int n_base = (tid & 15) << 3;

    const float* Ap = g_h + ((size_t)e * CAP + row0) * HDIM;
    const float* Bp = w2 + ((size_t)e * DMODEL + n0) * HDIM;

    float acc[8][8];
#pragma unroll
    for (int i = 0; i < 8; i++)
#pragma unroll
        for (int j = 0; j < 8; j++) acc[i][j] = 0.f;

    for (int k0 = 0; k0 < HDIM; k0 += 32) {
#pragma unroll
        for (int i = 0; i < 4; i++) {
            const int q = tid + i * 256;
            const int r = q >> 3, c = q & 7;
            const float4 v = *(const float4*)(Ap + (size_t)r * HDIM + k0 + (c << 2));
            sA[c * 4 + 0][r] = v.x; sA[c * 4 + 1][r] = v.y;
            sA[c * 4 + 2][r] = v.z; sA[c * 4 + 3][r] = v.w;
            const float4 u = *(const float4*)(Bp + (size_t)r * HDIM + k0 + (c << 2));
            sB[c * 4 + 0][r] = u.x; sB[c * 4 + 1][r] = u.y;
            sB[c * 4 + 2][r] = u.z; sB[c * 4 + 3][r] = u.w;
        }
        __syncthreads();
#pragma unroll
        for (int kk = 0; kk < 32; kk++) {
            const float4 a0 = *(const float4*)&sA[kk][m_base];
            const float4 a1 = *(const float4*)&sA[kk][m_base + 4];
            const float4 b0 = *(const float4*)&sB[kk][n_base];
            const float4 b1 = *(const float4*)&sB[kk][n_base + 4];
            const float a[8] = {a0.x, a0.y, a0.z, a0.w, a1.x, a1.y, a1.z, a1.w};
            const float b[8] = {b0.x, b0.y, b0.z, b0.w, b1.x, b1.y, b1.z, b1.w};
#pragma unroll
            for (int mi = 0; mi < 8; mi++)
#pragma unroll
                for (int ni = 0; ni < 8; ni++)
                    acc[mi][ni] += a[mi] * b[ni];
        }
        __syncthreads();
    }

    const int*   tokp = g_tok  + e * CAP + row0;
    const float* gp   = g_gate + e * CAP + row0;
#pragma unroll
    for (int mi = 0; mi < 8; mi++) {
        const int m = m_base + mi;
        if (row0 + m < cnt) {
            const int   t = tokp[m];
            const float g = gp[m];
            float* op = out + (size_t)t * DMODEL + n0 + n_base;
#pragma unroll
            for (int ni = 0; ni < 8; ni++)
                atomicAdd(op + ni, acc[mi][ni] * g);
        }
    }
}

// ---------------------------------------------------------------------------
extern "C" void kernel_launch(void* const* d_in, const int* in_sizes, int n_in,
                              void* d_out, int out_size)
{
    const float* x      = (const float*)d_in[0];
    const float* noise  = (const float*)d_in[1];
    const float* rw     = (const float*)d_in[2];
    const float* rb     = (const float*)d_in[3];
    const float* nw     = (const float*)d_in[4];
    const float* nb     = (const float*)d_in[5];
    const float* w1     = (const float*)d_in[6];
    const float* w2     = (const float*)d_in[7];
    const float* w3     = (const float*)d_in[8];
    float* out = (float*)d_out;

    void* cntp = nullptr;
    cudaGetSymbolAddress(&cntp, g_cnt);
    cudaMemsetAsync(cntp, 0, NEXP * sizeof(int));
    cudaMemsetAsync(out, 0, (size_t)T_TOK * DMODEL * sizeof(float));

    k_router<<<T_TOK / 4, 128>>>(x, noise, rw, rb, nw, nb);

    dim3 g1(CAP / 128, HDIM / 64, NEXP);
    k_gemm1<<<g1, 256>>>(x, w1, w3);

    dim3 g2(CAP / 128, DMODEL / 128, NEXP);
    k_gemm2<<<g2, 256>>>(w2, out);
}

// round 3
// speedup vs baseline: 3.7059x; 3.7059x over previous
#include <cuda_runtime.h>
#include <math.h>
#include <stdint.h>

#define T_TOK  8192
#define DMODEL 1024
#define HDIM   2048
#define NEXP   8
#define CAP    8192

#define LDK    36                 // padded row length in floats (32 data + 4 pad)
#define ROWB   (LDK * 4)          // 144 bytes per SMEM row
#define ABUF   (128 * ROWB)       // 18432 B per 128x32 tile
#define SMEM_BYTES (4 * ABUF)     // A0,B0,A1,B1 = 73728 B
#define SC_LD  132                // C staging stride (floats)

// ---------------- device scratch (static, allocation-free) ----------------
__device__ int   g_cnt[NEXP];
__device__ int   g_tok[NEXP * CAP];
__device__ float g_gate[NEXP * CAP];
__device__ float g_h[(size_t)NEXP * CAP * HDIM];

// ---------------- PTX helpers (all plain sm_80-class, no 'a' features) ----
__device__ __forceinline__ uint32_t smem_u32(const void* p) {
    uint32_t a;
    asm("{ .reg .u64 t; cvta.to.shared.u64 t, %1; cvt.u32.u64 %0, t; }" : "=r"(a) : "l"(p));
    return a;
}

#define CP_ASYNC16(dst, src) \
    asm volatile("cp.async.cg.shared.global [%0], [%1], 16;" :: "r"(dst), "l"(src))
#define CP_COMMIT() asm volatile("cp.async.commit_group;" ::: "memory")
#define CP_WAIT(n)  asm volatile("cp.async.wait_group %0;" :: "n"(n) : "memory")

__device__ __forceinline__ void ldsm_x4(uint32_t* r, uint32_t addr) {
    asm volatile("ldmatrix.sync.aligned.m8n8.x4.shared.b16 {%0,%1,%2,%3}, [%4];"
                 : "=r"(r[0]), "=r"(r[1]), "=r"(r[2]), "=r"(r[3]) : "r"(addr));
}
__device__ __forceinline__ void ldsm_x2(uint32_t* r, uint32_t addr) {
    asm volatile("ldmatrix.sync.aligned.m8n8.x2.shared.b16 {%0,%1}, [%2];"
                 : "=r"(r[0]), "=r"(r[1]) : "r"(addr));
}
__device__ __forceinline__ void to_tf32(uint32_t& x) {
    asm("cvt.rna.tf32.f32 %0, %0;" : "+r"(x));
}
__device__ __forceinline__ void mma_tf32(float* c, const uint32_t* a, const uint32_t* b) {
    asm volatile("mma.sync.aligned.m16n8k8.row.col.f32.tf32.tf32.f32 "
                 "{%0,%1,%2,%3}, {%4,%5,%6,%7}, {%8,%9}, {%0,%1,%2,%3};"
                 : "+f"(c[0]), "+f"(c[1]), "+f"(c[2]), "+f"(c[3])
                 : "r"(a[0]), "r"(a[1]), "r"(a[2]), "r"(a[3]), "r"(b[0]), "r"(b[1]));
}

// ---------------------------------------------------------------------------
// Router: one warp per token.
// ---------------------------------------------------------------------------
__global__ void __launch_bounds__(128) k_router(
    const float* __restrict__ x, const float* __restrict__ noise,
    const float* __restrict__ rw, const float* __restrict__ rb,
    const float* __restrict__ nw, const float* __restrict__ nb)
{
    const int warp = threadIdx.x >> 5;
    const int lane = threadIdx.x & 31;
    const int t = blockIdx.x * 4 + warp;

    const float* xr = x + (size_t)t * DMODEL;

    float accR[NEXP], accN[NEXP];
#pragma unroll
    for (int j = 0; j < NEXP; j++) { accR[j] = 0.f; accN[j] = 0.f; }

    for (int d = lane; d < DMODEL; d += 32) {
        const float xv = xr[d];
#pragma unroll
        for (int j = 0; j < NEXP; j++) {
            accR[j] += xv * rw[j * DMODEL + d];
            accN[j] += xv * nw[j * DMODEL + d];
        }
    }
#pragma unroll
    for (int j = 0; j < NEXP; j++) {
#pragma unroll
        for (int o = 16; o > 0; o >>= 1) {
            accR[j] += __shfl_xor_sync(0xffffffffu, accR[j], o);
            accN[j] += __shfl_xor_sync(0xffffffffu, accN[j], o);
        }
    }

    if (lane == 0) {
        float noisy[NEXP];
#pragma unroll
        for (int j = 0; j < NEXP; j++) {
            const float z  = accN[j] + nb[j];
            const float sp = (z > 20.f) ? z : log1pf(expf(z));
            noisy[j] = accR[j] + rb[j] + noise[(size_t)t * NEXP + j] * sp;
        }
        int i0 = 0;
#pragma unroll
        for (int j = 1; j < NEXP; j++) if (noisy[j] > noisy[i0]) i0 = j;
        int i1 = (i0 == 0) ? 1 : 0;
#pragma unroll
        for (int j = 0; j < NEXP; j++)
            if (j != i0 && noisy[j] > noisy[i1]) i1 = j;

        const float v0 = noisy[i0], v1 = noisy[i1];
        const float g0 = 1.f / (1.f + expf(v1 - v0));
        const float g1 = 1.f / (1.f + expf(v0 - v1));

        int p0 = atomicAdd(&g_cnt[i0], 1);
        g_tok[i0 * CAP + p0]  = t;
        g_gate[i0 * CAP + p0] = g0;
        int p1 = atomicAdd(&g_cnt[i1], 1);
        g_tok[i1 * CAP + p1]  = t;
        g_gate[i1 * CAP + p1] = g1;
    }
}

// ---------------------------------------------------------------------------
// Shared mainloop compute: one k-tile (32) of HMMA tf32 on SMEM buffers.
// Warp tile 64(M) x 32(N): 4 m-frags x 4 n-frags, 4 k-steps of 8.
// ---------------------------------------------------------------------------
__device__ __forceinline__ void compute_ktile(
    uint32_t aBase, uint32_t bBase, float acc[4][4][4])
{
#pragma unroll
    for (int ks = 0; ks < 4; ks++) {
        uint32_t af[4][4], bf[4][2];
#pragma unroll
        for (int mi = 0; mi < 4; mi++) {
            ldsm_x4(af[mi], aBase + (mi * 16 * LDK + ks * 8) * 4);
#pragma unroll
            for (int j = 0; j < 4; j++) to_tf32(af[mi][j]);
        }
#pragma unroll
        for (int ni = 0; ni < 4; ni++) {
            ldsm_x2(bf[ni], bBase + (ni * 8 * LDK + ks * 8) * 4);
            to_tf32(bf[ni][0]); to_tf32(bf[ni][1]);
        }
#pragma unroll
        for (int mi = 0; mi < 4; mi++)
#pragma unroll
            for (int ni = 0; ni < 4; ni++)
                mma_tf32(acc[mi][ni], af[mi], bf[ni]);
    }
}

// Store warp accumulators to SMEM C staging [128][SC_LD].
__device__ __forceinline__ void stage_C(
    float* sC, int warp_m, int warp_n, int lane, float acc[4][4][4])
{
    const int lr = lane >> 2;
    const int lc = (lane & 3) * 2;
#pragma unroll
    for (int mi = 0; mi < 4; mi++)
#pragma unroll
        for (int ni = 0; ni < 4; ni++) {
            float* p = sC + (warp_m + mi * 16 + lr) * SC_LD + warp_n + ni * 8 + lc;
            p[0] = acc[mi][ni][0];
            p[1] = acc[mi][ni][1];
            p[8 * SC_LD]     = acc[mi][ni][2];
            p[8 * SC_LD + 1] = acc[mi][ni][3];
        }
}

// ---------------------------------------------------------------------------
// GEMM1: C[128 x 128] where N cols [0,64) = X@w1^T slice, [64,128) = X@w3^T.
// Epilogue fuses SwiGLU and writes g_h[slot][n0..n0+64).
// ---------------------------------------------------------------------------
__global__ void __launch_bounds__(256, 2) k_gemm1(
    const float* __restrict__ x,
    const float* __restrict__ w1, const float* __restrict__ w3)
{
    const int e    = blockIdx.z;
    const int cnt  = g_cnt[e];
    const int row0 = blockIdx.x * 128;
    if (row0 >= cnt) return;
    const int n0 = blockIdx.y * 64;

    extern __shared__ char dynsmem[];
    const uint32_t sbu = smem_u32(dynsmem);

    const int tid  = threadIdx.x;
    const int warp = tid >> 5;
    const int lane = tid & 31;
    const int warp_m = (warp >> 2) * 64;
    const int warp_n = (warp & 3) * 32;

    // loader mapping: 1024 16B segments per tile, 4 per thread
    const int* tokp = g_tok + e * CAP + row0;
    const float* aSrc[4]; const float* bSrc[4];
    uint32_t dOff[4];
#pragma unroll
    for (int i = 0; i < 4; i++) {
        const int idx = i * 256 + tid;
        const int r = idx >> 3, seg = idx & 7;
        const int tk = (row0 + r < cnt) ? tokp[r] : 0;
        aSrc[i] = x + (size_t)tk * DMODEL + seg * 4;
        bSrc[i] = (r < 64)
                ? w1 + ((size_t)e * HDIM + n0 + r)      * DMODEL + seg * 4
                : w3 + ((size_t)e * HDIM + n0 + r - 64) * DMODEL + seg * 4;
        dOff[i] = (uint32_t)(r * ROWB + seg * 16);
    }

    // ldmatrix per-lane address bases
    const int aRow = (lane & 7) + ((lane >> 3) & 1) * 8;   // 0..15
    const int aCol = (lane >> 4) * 4;                      // 0 or 4
    const int l2   = lane & 15;
    const int bRow = l2 & 7;
    const int bCol = (l2 >> 3) * 4;

    float acc[4][4][4];
#pragma unroll
    for (int a = 0; a < 4; a++)
#pragma unroll
        for (int b = 0; b < 4; b++)
#pragma unroll
            for (int c = 0; c < 4; c++) acc[a][b][c] = 0.f;

    // prologue: load k-tile 0 into buf 0
#pragma unroll
    for (int i = 0; i < 4; i++) {
        CP_ASYNC16(sbu + dOff[i], aSrc[i]);
        CP_ASYNC16(sbu + ABUF + dOff[i], bSrc[i]);
    }
    CP_COMMIT();

    const int NKT = DMODEL / 32;
    for (int it = 0; it < NKT; ++it) {
        const int s = it & 1;
        if (it + 1 < NKT) {
            const uint32_t nb = sbu + ((it + 1) & 1) * (2 * ABUF);
            const int k0 = (it + 1) * 32;
#pragma unroll
            for (int i = 0; i < 4; i++) {
                CP_ASYNC16(nb + dOff[i], aSrc[i] + k0);
                CP_ASYNC16(nb + ABUF + dOff[i], bSrc[i] + k0);
            }
            CP_COMMIT();
            CP_WAIT(1);
        } else {
            CP_WAIT(0);
        }
        __syncthreads();
        const uint32_t ab = sbu + s * (2 * ABUF)
                          + (uint32_t)((warp_m + aRow) * LDK + aCol) * 4;
        const uint32_t bb = sbu + s * (2 * ABUF) + ABUF
                          + (uint32_t)((warp_n + bRow) * LDK + bCol) * 4;
        compute_ktile(ab, bb, acc);
        __syncthreads();
    }

    // stage C, then fused SwiGLU epilogue
    float* sC = (float*)dynsmem;
    stage_C(sC, warp_m, warp_n, lane, acc);
    __syncthreads();

    const int r    = tid >> 1;
    const int half = tid & 1;
    float* hp = g_h + ((size_t)e * CAP + row0 + r) * HDIM + n0;
    const float* c1 = sC + r * SC_LD + half * 32;
    const float* c3 = c1 + 64;
#pragma unroll
    for (int j = 0; j < 32; j += 4) {
        float4 o;
        float v;
        v = c1[j + 0]; o.x = (v / (1.f + expf(-v))) * c3[j + 0];
        v = c1[j + 1]; o.y = (v / (1.f + expf(-v))) * c3[j + 1];
        v = c1[j + 2]; o.z = (v / (1.f + expf(-v))) * c3[j + 2];
        v = c1[j + 3]; o.w = (v / (1.f + expf(-v))) * c3[j + 3];
        *(float4*)(hp + half * 32 + j) = o;
    }
}

// ---------------------------------------------------------------------------
// GEMM2: out[tok] += gate * (h @ w2^T), tile 128 x 128, K = 2048.
// ---------------------------------------------------------------------------
__global__ void __launch_bounds__(256, 2) k_gemm2(
    const float* __restrict__ w2, float* __restrict__ out)
{
    const int e    = blockIdx.z;
    const int cnt  = g_cnt[e];
    const int row0 = blockIdx.x * 128;
    if (row0 >= cnt) return;
    const int n0 = blockIdx.y * 128;

    extern __shared__ char dynsmem[];
    const uint32_t sbu = smem_u32(dynsmem);

    const int tid  = threadIdx.x;
    const int warp = tid >> 5;
    const int lane = tid & 31;
    const int warp_m = (warp >> 2) * 64;
    const int warp_n = (warp & 3) * 32;

    const float* aSrc[4]; const float* bSrc[4];
    uint32_t dOff[4];
#pragma unroll
    for (int i = 0; i < 4; i++) {
        const int idx = i * 256 + tid;
        const int r = idx >> 3, seg = idx & 7;
        aSrc[i] = g_h + ((size_t)e * CAP + row0 + r) * HDIM + seg * 4;
        bSrc[i] = w2  + ((size_t)e * DMODEL + n0 + r) * HDIM + seg * 4;
        dOff[i] = (uint32_t)(r * ROWB + seg * 16);
    }

    const int aRow = (lane & 7) + ((lane >> 3) & 1) * 8;
    const int aCol = (lane >> 4) * 4;
    const int l2   = lane & 15;
    const int bRow = l2 & 7;
    const int bCol = (l2 >> 3) * 4;

    float acc[4][4][4];
#pragma unroll
    for (int a = 0; a < 4; a++)
#pragma unroll
        for (int b = 0; b < 4; b++)
#pragma unroll
            for (int c = 0; c < 4; c++) acc[a][b][c] = 0.f;

#pragma unroll
    for (int i = 0; i < 4; i++) {
        CP_ASYNC16(sbu + dOff[i], aSrc[i]);
        CP_ASYNC16(sbu + ABUF + dOff[i], bSrc[i]);
    }
    CP_COMMIT();

    const int NKT = HDIM / 32;
    for (int it = 0; it < NKT; ++it) {
        const int s = it & 1;
        if (it + 1 < NKT) {
            const uint32_t nb = sbu + ((it + 1) & 1) * (2 * ABUF);
            const int k0 = (it + 1) * 32;
#pragma unroll
            for (int i = 0; i < 4; i++) {
                CP_ASYNC16(nb + dOff[i], aSrc[i] + k0);
                CP_ASYNC16(nb + ABUF + dOff[i], bSrc[i] + k0);
            }
            CP_COMMIT();
            CP_WAIT(1);
        } else {
            CP_WAIT(0);
        }
        __syncthreads();
        const uint32_t ab = sbu + s * (2 * ABUF)
                          + (uint32_t)((warp_m + aRow) * LDK + aCol) * 4;
        const uint32_t bb = sbu + s * (2 * ABUF) + ABUF
                          + (uint32_t)((warp_n + bRow) * LDK + bCol) * 4;
        compute_ktile(ab, bb, acc);
        __syncthreads();
    }

    float* sC = (float*)dynsmem;
    stage_C(sC, warp_m, warp_n, lane, acc);
    __syncthreads();

    const int r    = tid >> 1;
    const int half = tid & 1;
    const int m = row0 + r;
    if (m < cnt) {
        const int   t = g_tok [e * CAP + m];
        const float g = g_gate[e * CAP + m];
        float* op = out + (size_t)t * DMODEL + n0 + half * 64;
        const float* cp = sC + r * SC_LD + half * 64;
#pragma unroll
        for (int j = 0; j < 64; j++)
            atomicAdd(op + j, cp[j] * g);
    }
}

// ---------------------------------------------------------------------------
extern "C" void kernel_launch(void* const* d_in, const int* in_sizes, int n_in,
                              void* d_out, int out_size)
{
    const float* x     = (const float*)d_in[0];
    const float* noise = (const float*)d_in[1];
    const float* rw    = (const float*)d_in[2];
    const float* rb    = (const float*)d_in[3];
    const float* nw    = (const float*)d_in[4];
    const float* nb    = (const float*)d_in[5];
    const float* w1    = (const float*)d_in[6];
    const float* w2    = (const float*)d_in[7];
    const float* w3    = (const float*)d_in[8];
    float* out = (float*)d_out;

    cudaFuncSetAttribute(k_gemm1, cudaFuncAttributeMaxDynamicSharedMemorySize, SMEM_BYTES);
    cudaFuncSetAttribute(k_gemm2, cudaFuncAttributeMaxDynamicSharedMemorySize, SMEM_BYTES);

    void* cntp = nullptr;
    cudaGetSymbolAddress(&cntp, g_cnt);
    cudaMemsetAsync(cntp, 0, NEXP * sizeof(int));
    cudaMemsetAsync(out, 0, (size_t)T_TOK * DMODEL * sizeof(float));

    k_router<<<T_TOK / 4, 128>>>(x, noise, rw, rb, nw, nb);

    dim3 g1(CAP / 128, HDIM / 64, NEXP);
    k_gemm1<<<g1, 256, SMEM_BYTES>>>(x, w1, w3);

    dim3 g2(CAP / 128, DMODEL / 128, NEXP);
    k_gemm2<<<g2, 256, SMEM_BYTES>>>(w2, out);
}

// round 4
// speedup vs baseline: 7.2279x; 1.9504x over previous
#include <cuda_runtime.h>
#include <cuda_fp16.h>
#include <math.h>
#include <stdint.h>

#define T_TOK  8192
#define DMODEL 1024
#define HDIM   2048
#define NEXP   8
#define CAP    8192

#define KTILE  64                         // k-tile in halves (128 B rows)
#define ABUF   (128 * 128)                // 16384 B per 128 x 64-half tile
#define STAGE  (2 * ABUF)                 // A + B per stage
#define SMEM_BYTES (3 * STAGE)            // 98304 B, 3-stage pipeline
#define SC_LD  132                        // fp32 C staging stride

// ---------------- device scratch (static, allocation-free) ----------------
__device__ int    g_cnt[NEXP];
__device__ int    g_tok[NEXP * CAP];
__device__ float  g_gate[NEXP * CAP];
__device__ __half g_xh[(size_t)T_TOK * DMODEL];
__device__ __half g_w1h[(size_t)NEXP * HDIM * DMODEL];
__device__ __half g_w3h[(size_t)NEXP * HDIM * DMODEL];
__device__ __half g_w2h[(size_t)NEXP * DMODEL * HDIM];
__device__ __half g_hh[(size_t)NEXP * CAP * HDIM];

// ---------------- PTX helpers (plain sm_80-class) ----------------
__device__ __forceinline__ uint32_t smem_u32(const void* p) {
    uint32_t a;
    asm("{ .reg .u64 t; cvta.to.shared.u64 t, %1; cvt.u32.u64 %0, t; }" : "=r"(a) : "l"(p));
    return a;
}
#define CP_ASYNC16(dst, src) \
    asm volatile("cp.async.cg.shared.global [%0], [%1], 16;" :: "r"(dst), "l"(src))
#define CP_COMMIT() asm volatile("cp.async.commit_group;" ::: "memory")
#define CP_WAIT(n)  asm volatile("cp.async.wait_group %0;" :: "n"(n) : "memory")

__device__ __forceinline__ void ldsm_x4(uint32_t* r, uint32_t addr) {
    asm volatile("ldmatrix.sync.aligned.m8n8.x4.shared.b16 {%0,%1,%2,%3}, [%4];"
                 : "=r"(r[0]), "=r"(r[1]), "=r"(r[2]), "=r"(r[3]) : "r"(addr));
}
__device__ __forceinline__ void mma_f16(float* c, const uint32_t* a, const uint32_t* b) {
    asm volatile("mma.sync.aligned.m16n8k16.row.col.f32.f16.f16.f32 "
                 "{%0,%1,%2,%3}, {%4,%5,%6,%7}, {%8,%9}, {%0,%1,%2,%3};"
                 : "+f"(c[0]), "+f"(c[1]), "+f"(c[2]), "+f"(c[3])
                 : "r"(a[0]), "r"(a[1]), "r"(a[2]), "r"(a[3]), "r"(b[0]), "r"(b[1]));
}
__device__ __forceinline__ uint32_t pack2(float lo, float hi) {
    __half2 h = __floats2half2_rn(lo, hi);
    return *reinterpret_cast<uint32_t*>(&h);
}

// swizzled smem byte offset for row r (128B rows), 16B segment s (0..7)
#define SWOFF(r, s16) ((uint32_t)((r) * 128 + (((s16) * 16) ^ (((r) & 7) << 4))))

// ---------------------------------------------------------------------------
// fp32 -> fp16 bulk convert (8 elems / thread)
// ---------------------------------------------------------------------------
__global__ void __launch_bounds__(256) k_cvt(
    const float4* __restrict__ s, uint4* __restrict__ d, int n8)
{
    const int i = blockIdx.x * 256 + threadIdx.x;
    if (i >= n8) return;
    const float4 a = s[2 * i], b = s[2 * i + 1];
    uint4 o;
    o.x = pack2(a.x, a.y); o.y = pack2(a.z, a.w);
    o.z = pack2(b.x, b.y); o.w = pack2(b.z, b.w);
    d[i] = o;
}

// ---------------------------------------------------------------------------
// Router: one warp per token; also emits x in fp16 (free: already reads x).
// ---------------------------------------------------------------------------
__global__ void __launch_bounds__(128) k_router(
    const float* __restrict__ x, const float* __restrict__ noise,
    const float* __restrict__ rw, const float* __restrict__ rb,
    const float* __restrict__ nw, const float* __restrict__ nb)
{
    const int warp = threadIdx.x >> 5;
    const int lane = threadIdx.x & 31;
    const int t = blockIdx.x * 4 + warp;

    const float* xr = x + (size_t)t * DMODEL;
    __half* xh = g_xh + (size_t)t * DMODEL;

    float accR[NEXP], accN[NEXP];
#pragma unroll
    for (int j = 0; j < NEXP; j++) { accR[j] = 0.f; accN[j] = 0.f; }

    for (int d = lane; d < DMODEL; d += 32) {
        const float xv = xr[d];
        xh[d] = __float2half_rn(xv);
#pragma unroll
        for (int j = 0; j < NEXP; j++) {
            accR[j] += xv * rw[j * DMODEL + d];
            accN[j] += xv * nw[j * DMODEL + d];
        }
    }
#pragma unroll
    for (int j = 0; j < NEXP; j++) {
#pragma unroll
        for (int o = 16; o > 0; o >>= 1) {
            accR[j] += __shfl_xor_sync(0xffffffffu, accR[j], o);
            accN[j] += __shfl_xor_sync(0xffffffffu, accN[j], o);
        }
    }

    if (lane == 0) {
        float noisy[NEXP];
#pragma unroll
        for (int j = 0; j < NEXP; j++) {
            const float z  = accN[j] + nb[j];
            const float sp = (z > 20.f) ? z : log1pf(expf(z));
            noisy[j] = accR[j] + rb[j] + noise[(size_t)t * NEXP + j] * sp;
        }
        int i0 = 0;
#pragma unroll
        for (int j = 1; j < NEXP; j++) if (noisy[j] > noisy[i0]) i0 = j;
        int i1 = (i0 == 0) ? 1 : 0;
#pragma unroll
        for (int j = 0; j < NEXP; j++)
            if (j != i0 && noisy[j] > noisy[i1]) i1 = j;

        const float v0 = noisy[i0], v1 = noisy[i1];
        const float g0 = 1.f / (1.f + expf(v1 - v0));
        const float g1 = 1.f / (1.f + expf(v0 - v1));

        int p0 = atomicAdd(&g_cnt[i0], 1);
        g_tok[i0 * CAP + p0]  = t;
        g_gate[i0 * CAP + p0] = g0;
        int p1 = atomicAdd(&g_cnt[i1], 1);
        g_tok[i1 * CAP + p1]  = t;
        g_gate[i1 * CAP + p1] = g1;
    }
}

// ---------------------------------------------------------------------------
// One k-tile (64 halves) of fp16 HMMA. Warp tile 64(M) x 32(N).
// ---------------------------------------------------------------------------
__device__ __forceinline__ void compute_ktile(
    uint32_t stage, uint32_t aOff, uint32_t aSwz, uint32_t aKl,
    uint32_t bOff, uint32_t bSwz, uint32_t bKl, float acc[4][4][4])
{
#pragma unroll
    for (int ks = 0; ks < 4; ks++) {
        uint32_t af[4][4], bf[2][4];
        const uint32_t acb = ((uint32_t)(ks * 32) + aKl) ^ aSwz;
        const uint32_t bcb = ((uint32_t)(ks * 32) + bKl) ^ bSwz;
#pragma unroll
        for (int mi = 0; mi < 4; mi++)
            ldsm_x4(af[mi], stage + aOff + mi * 2048 + acb);
#pragma unroll
        for (int nj = 0; nj < 2; nj++)
            ldsm_x4(bf[nj], stage + bOff + nj * 2048 + bcb);
#pragma unroll
        for (int mi = 0; mi < 4; mi++)
#pragma unroll
            for (int ni = 0; ni < 4; ni++)
                mma_f16(acc[mi][ni], af[mi], &bf[ni >> 1][(ni & 1) * 2]);
    }
}

__device__ __forceinline__ void stage_C(
    float* sC, int warp_m, int warp_n, int lane, float acc[4][4][4])
{
    const int lr = lane >> 2;
    const int lc = (lane & 3) * 2;
#pragma unroll
    for (int mi = 0; mi < 4; mi++)
#pragma unroll
        for (int ni = 0; ni < 4; ni++) {
            float* p = sC + (warp_m + mi * 16 + lr) * SC_LD + warp_n + ni * 8 + lc;
            p[0] = acc[mi][ni][0];
            p[1] = acc[mi][ni][1];
            p[8 * SC_LD]     = acc[mi][ni][2];
            p[8 * SC_LD + 1] = acc[mi][ni][3];
        }
}

// ---------------------------------------------------------------------------
// GEMM1 (fp16): C[128x128]: cols [0,64)=X@w1^T slice, [64,128)=X@w3^T slice.
// Epilogue: SwiGLU -> g_hh (fp16).
// ---------------------------------------------------------------------------
__global__ void __launch_bounds__(256, 2) k_gemm1()
{
    const int e    = blockIdx.z;
    const int cnt  = g_cnt[e];
    const int row0 = blockIdx.x * 128;
    if (row0 >= cnt) return;
    const int n0 = blockIdx.y * 64;

    extern __shared__ char dynsmem[];
    const uint32_t sbu = smem_u32(dynsmem);

    const int tid  = threadIdx.x;
    const int warp = tid >> 5;
    const int lane = tid & 31;
    const int warp_m = (warp >> 2) * 64;
    const int warp_n = (warp & 3) * 32;

    // loader mapping: 1024 16B segments per tile, 4 per thread
    const int* tokp = g_tok + e * CAP + row0;
    const __half* aSrc[4]; const __half* bSrc[4];
    uint32_t dOff[4];
#pragma unroll
    for (int i = 0; i < 4; i++) {
        const int idx = i * 256 + tid;
        const int r = idx >> 3, seg = idx & 7;
        const int tk = (row0 + r < cnt) ? tokp[r] : 0;
        aSrc[i] = g_xh + (size_t)tk * DMODEL + seg * 8;
        bSrc[i] = (r < 64)
                ? g_w1h + ((size_t)e * HDIM + n0 + r)      * DMODEL + seg * 8
                : g_w3h + ((size_t)e * HDIM + n0 + r - 64) * DMODEL + seg * 8;
        dOff[i] = SWOFF(r, seg);
    }

    // per-lane ldmatrix precomputes
    const int aR = warp_m + (lane & 15);
    const uint32_t aOff = (uint32_t)aR * 128;
    const uint32_t aSwz = (uint32_t)(aR & 7) << 4;
    const uint32_t aKl  = (uint32_t)(lane >> 4) << 4;
    const int bR = warp_n + ((lane >> 4) << 3) + (lane & 7);
    const uint32_t bOff = (uint32_t)ABUF + (uint32_t)bR * 128;
    const uint32_t bSwz = (uint32_t)(bR & 7) << 4;
    const uint32_t bKl  = ((uint32_t)(lane >> 3) & 1) << 4;

    float acc[4][4][4];
#pragma unroll
    for (int a = 0; a < 4; a++)
#pragma unroll
        for (int b = 0; b < 4; b++)
#pragma unroll
            for (int c = 0; c < 4; c++) acc[a][b][c] = 0.f;

    // prologue: tiles 0 and 1
#pragma unroll
    for (int p = 0; p < 2; p++) {
        const uint32_t sb = sbu + p * STAGE;
#pragma unroll
        for (int i = 0; i < 4; i++) {
            CP_ASYNC16(sb + dOff[i],        aSrc[i] + p * KTILE);
            CP_ASYNC16(sb + ABUF + dOff[i], bSrc[i] + p * KTILE);
        }
        CP_COMMIT();
    }

    const int NKT = DMODEL / KTILE;   // 16
    for (int it = 0; it < NKT; ++it) {
        CP_WAIT(1);
        __syncthreads();
        compute_ktile(sbu + (it % 3) * STAGE, aOff, aSwz, aKl, bOff, bSwz, bKl, acc);
        if (it + 2 < NKT) {
            const uint32_t sb = sbu + ((it + 2) % 3) * STAGE;
            const int k0 = (it + 2) * KTILE;
#pragma unroll
            for (int i = 0; i < 4; i++) {
                CP_ASYNC16(sb + dOff[i],        aSrc[i] + k0);
                CP_ASYNC16(sb + ABUF + dOff[i], bSrc[i] + k0);
            }
        }
        CP_COMMIT();
    }
    __syncthreads();

    float* sC = (float*)dynsmem;
    stage_C(sC, warp_m, warp_n, lane, acc);
    __syncthreads();

    const int r    = tid >> 1;
    const int half = tid & 1;
    const float* c1 = sC + r * SC_LD + half * 32;
    const float* c3 = c1 + 64;
    __half* hp = g_hh + ((size_t)e * CAP + row0 + r) * HDIM + n0 + half * 32;
#pragma unroll
    for (int j = 0; j < 32; j += 8) {
        float s[8];
#pragma unroll
        for (int q = 0; q < 8; q++) {
            const float v = c1[j + q];
            s[q] = (v / (1.f + expf(-v))) * c3[j + q];
        }
        uint4 o;
        o.x = pack2(s[0], s[1]); o.y = pack2(s[2], s[3]);
        o.z = pack2(s[4], s[5]); o.w = pack2(s[6], s[7]);
        *(uint4*)(hp + j) = o;
    }
}

// ---------------------------------------------------------------------------
// GEMM2 (fp16): out[tok] += gate * (h @ w2^T), tile 128 x 128, K = 2048.
// ---------------------------------------------------------------------------
__global__ void __launch_bounds__(256, 2) k_gemm2(float* __restrict__ out)
{
    const int e    = blockIdx.z;
    const int cnt  = g_cnt[e];
    const int row0 = blockIdx.x * 128;
    if (row0 >= cnt) return;
    const int n0 = blockIdx.y * 128;

    extern __shared__ char dynsmem[];
    const uint32_t sbu = smem_u32(dynsmem);

    const int tid  = threadIdx.x;
    const int warp = tid >> 5;
    const int lane = tid & 31;
    const int warp_m = (warp >> 2) * 64;
    const int warp_n = (warp & 3) * 32;

    const __half* aSrc[4]; const __half* bSrc[4];
    uint32_t dOff[4];
#pragma unroll
    for (int i = 0; i < 4; i++) {
        const int idx = i * 256 + tid;
        const int r = idx >> 3, seg = idx & 7;
        aSrc[i] = g_hh  + ((size_t)e * CAP + row0 + r) * HDIM + seg * 8;
        bSrc[i] = g_w2h + ((size_t)e * DMODEL + n0 + r) * HDIM + seg * 8;
        dOff[i] = SWOFF(r, seg);
    }

    const int aR = warp_m + (lane & 15);
    const uint32_t aOff = (uint32_t)aR * 128;
    const uint32_t aSwz = (uint32_t)(aR & 7) << 4;
    const uint32_t aKl  = (uint32_t)(lane >> 4) << 4;
    const int bR = warp_n + ((lane >> 4) << 3) + (lane & 7);
    const uint32_t bOff = (uint32_t)ABUF + (uint32_t)bR * 128;
    const uint32_t bSwz = (uint32_t)(bR & 7) << 4;
    const uint32_t bKl  = ((uint32_t)(lane >> 3) & 1) << 4;

    float acc[4][4][4];
#pragma unroll
    for (int a = 0; a < 4; a++)
#pragma unroll
        for (int b = 0; b < 4; b++)
#pragma unroll
            for (int c = 0; c < 4; c++) acc[a][b][c] = 0.f;

#pragma unroll
    for (int p = 0; p < 2; p++) {
        const uint32_t sb = sbu + p * STAGE;
#pragma unroll
        for (int i = 0; i < 4; i++) {
            CP_ASYNC16(sb + dOff[i],        aSrc[i] + p * KTILE);
            CP_ASYNC16(sb + ABUF + dOff[i], bSrc[i] + p * KTILE);
        }
        CP_COMMIT();
    }

    const int NKT = HDIM / KTILE;   // 32
    for (int it = 0; it < NKT; ++it) {
        CP_WAIT(1);
        __syncthreads();
        compute_ktile(sbu + (it % 3) * STAGE, aOff, aSwz, aKl, bOff, bSwz, bKl, acc);
        if (it + 2 < NKT) {
            const uint32_t sb = sbu + ((it + 2) % 3) * STAGE;
            const int k0 = (it + 2) * KTILE;
#pragma unroll
            for (int i = 0; i < 4; i++) {
                CP_ASYNC16(sb + dOff[i],        aSrc[i] + k0);
                CP_ASYNC16(sb + ABUF + dOff[i], bSrc[i] + k0);
            }
        }
        CP_COMMIT();
    }
    __syncthreads();

    float* sC = (float*)dynsmem;
    stage_C(sC, warp_m, warp_n, lane, acc);
    __syncthreads();

    const int r    = tid >> 1;
    const int half = tid & 1;
    const int m = row0 + r;
    if (m < cnt) {
        const int   t = g_tok [e * CAP + m];
        const float g = g_gate[e * CAP + m];
        float* op = out + (size_t)t * DMODEL + n0 + half * 64;
        const float* cp = sC + r * SC_LD + half * 64;
#pragma unroll
        for (int j = 0; j < 64; j++)
            atomicAdd(op + j, cp[j] * g);
    }
}

// ---------------------------------------------------------------------------
extern "C" void kernel_launch(void* const* d_in, const int* in_sizes, int n_in,
                              void* d_out, int out_size)
{
    const float* x     = (const float*)d_in[0];
    const float* noise = (const float*)d_in[1];
    const float* rw    = (const float*)d_in[2];
    const float* rb    = (const float*)d_in[3];
    const float* nw    = (const float*)d_in[4];
    const float* nb    = (const float*)d_in[5];
    const float* w1    = (const float*)d_in[6];
    const float* w2    = (const float*)d_in[7];
    const float* w3    = (const float*)d_in[8];
    float* out = (float*)d_out;

    cudaFuncSetAttribute(k_gemm1, cudaFuncAttributeMaxDynamicSharedMemorySize, SMEM_BYTES);
    cudaFuncSetAttribute(k_gemm2, cudaFuncAttributeMaxDynamicSharedMemorySize, SMEM_BYTES);

    void* cntp = nullptr;
    cudaGetSymbolAddress(&cntp, g_cnt);
    cudaMemsetAsync(cntp, 0, NEXP * sizeof(int));
    cudaMemsetAsync(out, 0, (size_t)T_TOK * DMODEL * sizeof(float));

    // weight conversions (fp32 -> fp16)
    void *w1h = nullptr, *w3h = nullptr, *w2h = nullptr;
    cudaGetSymbolAddress(&w1h, g_w1h);
    cudaGetSymbolAddress(&w3h, g_w3h);
    cudaGetSymbolAddress(&w2h, g_w2h);
    const int nW8 = NEXP * HDIM * DMODEL / 8;   // 2097152
    k_cvt<<<nW8 / 256, 256>>>((const float4*)w1, (uint4*)w1h, nW8);
    k_cvt<<<nW8 / 256, 256>>>((const float4*)w3, (uint4*)w3h, nW8);
    k_cvt<<<nW8 / 256, 256>>>((const float4*)w2, (uint4*)w2h, nW8);

    k_router<<<T_TOK / 4, 128>>>(x, noise, rw, rb, nw, nb);

    dim3 g1(CAP / 128, HDIM / 64, NEXP);
    k_gemm1<<<g1, 256, SMEM_BYTES>>>();

    dim3 g2(CAP / 128, DMODEL / 128, NEXP);
    k_gemm2<<<g2, 256, SMEM_BYTES>>>(out);
}